// round 16
// baseline (speedup 1.0000x reference)
#include <cuda_runtime.h>
#include <cuda_fp16.h>
#include <cstdint>
#include <cstddef>

// ============================================================
// GAT attention head, N=8192, IN_F=128, OUT_F=64
//  h = X@W ; e = LeakyReLU(fs_i + fd_j) masked by adj ; softmax ; P@h ; elu
//
// exp(LR(fs+fd)) = max(E_i*E_j, G_i*G_j) -> no exp in N^2 loop.
// Fixed-max softmax -> single pass; fp16 P/h via mma.sync.m16n8k16.
//
// PERSISTENT: 444 CTAs (3/SM) own static contiguous ranges of 16384 tiles
// (64 row-blocks x 256 j-tiles of 32); flush by atomicAdd on row-block
// change. Per-rb completion counters: the LAST CTA to finish a row-block
// runs the divide+elu+store for its 128 rows inline (threadFenceReduction
// pattern) -> no separate finalize kernel.
// 3-stage cp.async pipeline, distance 2; adj XOR-4 chunk swizzle.
// ============================================================

#define NT 8192
#define IN_FEAT 128
#define OUT_FEAT 64
#define JTILE 32
#define NUM_RB 64
#define TOTAL_TILES 16384            // 64 rb x 256 j-tiles
#define WORKERS 444                  // 3 per SM x 148
#define ADJROW 128                   // 32*4, no pad (swizzled)
#define HROW 96                      // 32*2 + 32 pad: LDS.64 conflict-free

#define ADJ_BYTES (128 * ADJROW)     // 16384
#define H_BYTES   (OUT_FEAT * HROW)  // 6144
#define EG_BYTES  (JTILE * 8)        // 256
#define NSTAGE 3
#define OFF_ADJ(i) ((i) * ADJ_BYTES)
#define OFF_H(i)   (NSTAGE * ADJ_BYTES + (i) * H_BYTES)
#define OFF_EG(i)  (NSTAGE * ADJ_BYTES + NSTAGE * H_BYTES + (i) * EG_BYTES)
#define ATTN_SMEM  (NSTAGE * (ADJ_BYTES + H_BYTES + EG_BYTES))   // 68352

#define PREP_WS   0
#define PREP_XS   (IN_FEAT * OUT_FEAT * 4)            // 32768
#define PREP_HS   (PREP_XS + 32 * IN_FEAT * 4)        // 49152
#define HS_STRIDE 34
#define PREP_SMEM (PREP_HS + OUT_FEAT * HS_STRIDE * 2) // 53504

// ---------------- scratch (static device arrays; no allocation) ----------
__device__ __half g_ht[OUT_FEAT * NT];
__device__ float2 g_EGs[NT];
__device__ float2 g_EGd[NT];
__device__ float  g_num[NT * OUT_FEAT];
__device__ float  g_den[NT];
__device__ int    g_cnt[NUM_RB];

// ---------------- helpers ------------------------------------------------
__device__ __forceinline__ uint32_t smem_u32(const void* p) {
    uint32_t a;
    asm("{ .reg .u64 t; cvta.to.shared.u64 t, %1; cvt.u32.u64 %0, t; }"
        : "=r"(a) : "l"(p));
    return a;
}
__device__ __forceinline__ void cp16(uint32_t dst, const void* src) {
    asm volatile("cp.async.cg.shared.global [%0], [%1], 16;" :: "r"(dst), "l"(src));
}
__device__ __forceinline__ void cp8(uint32_t dst, const void* src) {
    asm volatile("cp.async.ca.shared.global [%0], [%1], 8;" :: "r"(dst), "l"(src));
}
#define CP_COMMIT() asm volatile("cp.async.commit_group;" ::: "memory")
#define CP_WAIT(n)  asm volatile("cp.async.wait_group %0;" :: "n"(n) : "memory")

__device__ __forceinline__ void mma16816(float* d, uint32_t a0, uint32_t a1,
                                         uint32_t a2, uint32_t a3,
                                         uint32_t b0, uint32_t b1) {
    asm volatile(
        "mma.sync.aligned.m16n8k16.row.col.f32.f16.f16.f32 "
        "{%0,%1,%2,%3}, {%4,%5,%6,%7}, {%8,%9}, {%0,%1,%2,%3};"
        : "+f"(d[0]), "+f"(d[1]), "+f"(d[2]), "+f"(d[3])
        : "r"(a0), "r"(a1), "r"(a2), "r"(a3), "r"(b0), "r"(b1));
}
__device__ __forceinline__ uint32_t packh2(float x, float y) {
    __half2 h = __floats2half2_rn(x, y);
    return *reinterpret_cast<uint32_t*>(&h);
}
// CTA index owning tile t (inverse of the static range split)
__device__ __forceinline__ int c_of(int t) {
    return (int)(((long long)(t + 1) * WORKERS - 1) / TOTAL_TILES);
}

// =========================================================================
// Kernel 0: zero accumulators + counters
// =========================================================================
__global__ void __launch_bounds__(256) zero_kernel() {
    int gid = blockIdx.x * 256 + threadIdx.x;
    ((float4*)g_num)[gid] = make_float4(0.f, 0.f, 0.f, 0.f);
    if (gid < NT / 4)
        ((float4*)g_den)[gid] = make_float4(0.f, 0.f, 0.f, 0.f);
    if (gid < NUM_RB) g_cnt[gid] = 0;
}

// =========================================================================
// Kernel 1: h = X@W ; EG tables ; h^T fp16 (coalesced via smem transpose).
// R9 shape (measured 11.07us): 256 blocks x 256 threads, 4 rows/warp.
// =========================================================================
__global__ void __launch_bounds__(256) prep_kernel(const float* __restrict__ x,
                                                   const float* __restrict__ W,
                                                   const float* __restrict__ a) {
    extern __shared__ __align__(16) char sm[];
    float*  Ws = (float*)(sm + PREP_WS);
    float*  xs = (float*)(sm + PREP_XS);
    __half* hs = (__half*)(sm + PREP_HS);   // [64 f][34]

    int tid = threadIdx.x;
    int i0 = blockIdx.x * 32;

    {
        const float4* W4 = (const float4*)W;
        float4* Ws4 = (float4*)Ws;
#pragma unroll
        for (int u = 0; u < 8; u++) Ws4[tid + u * 256] = W4[tid + u * 256];
        const float4* x4 = (const float4*)(x + (size_t)i0 * IN_FEAT);
        float4* xs4 = (float4*)xs;
#pragma unroll
        for (int u = 0; u < 4; u++) xs4[tid + u * 256] = x4[tid + u * 256];
    }
    __syncthreads();

    int w = tid >> 5, l = tid & 31;
    float acc[4][2];
#pragma unroll
    for (int rr = 0; rr < 4; rr++) { acc[rr][0] = 0.f; acc[rr][1] = 0.f; }

#pragma unroll 4
    for (int k4 = 0; k4 < IN_FEAT; k4 += 4) {
        float2 wv[4];
#pragma unroll
        for (int kk = 0; kk < 4; kk++)
            wv[kk] = *(const float2*)&Ws[(k4 + kk) * OUT_FEAT + 2 * l];
#pragma unroll
        for (int rr = 0; rr < 4; rr++) {
            float4 xv = *(const float4*)&xs[(w * 4 + rr) * IN_FEAT + k4];
            acc[rr][0] = fmaf(xv.x, wv[0].x, acc[rr][0]);
            acc[rr][1] = fmaf(xv.x, wv[0].y, acc[rr][1]);
            acc[rr][0] = fmaf(xv.y, wv[1].x, acc[rr][0]);
            acc[rr][1] = fmaf(xv.y, wv[1].y, acc[rr][1]);
            acc[rr][0] = fmaf(xv.z, wv[2].x, acc[rr][0]);
            acc[rr][1] = fmaf(xv.z, wv[2].y, acc[rr][1]);
            acc[rr][0] = fmaf(xv.w, wv[3].x, acc[rr][0]);
            acc[rr][1] = fmaf(xv.w, wv[3].y, acc[rr][1]);
        }
    }

#pragma unroll
    for (int rr = 0; rr < 4; rr++) {
        int il = w * 4 + rr;
        hs[(2 * l) * HS_STRIDE + il]     = __float2half(acc[rr][0]);
        hs[(2 * l + 1) * HS_STRIDE + il] = __float2half(acc[rr][1]);
    }

    float a0 = a[2 * l], a1 = a[2 * l + 1];
    float a2 = a[OUT_FEAT + 2 * l], a3 = a[OUT_FEAT + 2 * l + 1];
#pragma unroll
    for (int rr = 0; rr < 4; rr++) {
        float s = acc[rr][0] * a0 + acc[rr][1] * a1;
        float d = acc[rr][0] * a2 + acc[rr][1] * a3;
#pragma unroll
        for (int off = 16; off; off >>= 1) {
            s += __shfl_xor_sync(0xFFFFFFFFu, s, off);
            d += __shfl_xor_sync(0xFFFFFFFFu, d, off);
        }
        if (l == 0) {
            int i = i0 + w * 4 + rr;
            g_EGs[i] = make_float2(expf(s), expf(0.2f * s));
            g_EGd[i] = make_float2(expf(d), expf(0.2f * d));
        }
    }
    __syncthreads();

#pragma unroll
    for (int u = 0; u < 4; u++) {
        int id = tid + u * 256;
        int f = id >> 4, c = id & 15;
        uint32_t v = *(const uint32_t*)&hs[f * HS_STRIDE + 2 * c];
        *(uint32_t*)&g_ht[(size_t)f * NT + i0 + 2 * c] = v;
    }
}

// =========================================================================
// Kernel 2: persistent fused attention + inline last-finisher finalize.
// 444 CTAs x 256 thr, 3 CTAs/SM. Warp w: rows w*16..w*16+15, 32 j.
// =========================================================================
__global__ void __launch_bounds__(256, 3) attn_kernel(const int* __restrict__ adj,
                                                      float* __restrict__ out) {
    extern __shared__ __align__(16) char sm[];
    __shared__ int s_last;
    uint32_t sb = smem_u32(sm);

    int tid = threadIdx.x, w = tid >> 5, lane = tid & 31;
    int r = lane >> 2, q = lane & 3;
    int cta = blockIdx.x;

    int t0 = (int)(((long long)cta * TOTAL_TILES) / WORKERS);
    int t1 = (int)(((long long)(cta + 1) * TOTAL_TILES) / WORKERS);

    float acc[8][4];
#pragma unroll
    for (int nt = 0; nt < 8; nt++)
#pragma unroll
        for (int v = 0; v < 4; v++) acc[nt][v] = 0.f;
    float ds0 = 0.f, ds1 = 0.f;

    // stage one tile: adj (128x32 int, XOR-4 swizzled) + H (64x32 fp16) + EG
    auto issue_tile = [&](int buf, int t) {
        int i0t = (t >> 8) * 128;
        int j0t = (t & 255) * JTILE;
        uint32_t ab = sb + OFF_ADJ(buf);
        uint32_t hb = sb + OFF_H(buf);
        uint32_t eb = sb + OFF_EG(buf);
#pragma unroll
        for (int u = 0; u < 4; u++) {
            int id = tid + u * 256;
            int row = id >> 3, c = id & 7;
            int cs = c ^ ((row & 1) << 2);      // odd rows swap 64B halves
            cp16(ab + row * ADJROW + cs * 16,
                 &adj[(size_t)(i0t + row) * NT + j0t + c * 4]);
        }
        {
            int f = tid >> 2, c = tid & 3;
            cp16(hb + f * HROW + c * 16,
                 &g_ht[(size_t)f * NT + j0t + c * 8]);
        }
        if (tid < JTILE) cp8(eb + tid * 8, &g_EGd[j0t + tid]);
        CP_COMMIT();
    };

    int cur_rb = t0 >> 8;
    float2 egs0 = g_EGs[cur_rb * 128 + w * 16 + r];
    float2 egs1 = g_EGs[cur_rb * 128 + w * 16 + r + 8];

    // flush accumulators for rb via atomics (per-warp, no sync needed)
    auto flush = [&](int rb) {
        float d0 = ds0, d1 = ds1;
        d0 += __shfl_xor_sync(0xFFFFFFFFu, d0, 1);
        d0 += __shfl_xor_sync(0xFFFFFFFFu, d0, 2);
        d1 += __shfl_xor_sync(0xFFFFFFFFu, d1, 1);
        d1 += __shfl_xor_sync(0xFFFFFFFFu, d1, 2);
        int R = rb * 128 + w * 16 + r;
        if (q == 0) {
            atomicAdd(&g_den[R], d0);
            atomicAdd(&g_den[R + 8], d1);
        }
#pragma unroll
        for (int nt = 0; nt < 8; nt++) {
            int col = nt * 8 + q * 2;
            atomicAdd(&g_num[(size_t)R * OUT_FEAT + col],           acc[nt][0]);
            atomicAdd(&g_num[(size_t)R * OUT_FEAT + col + 1],       acc[nt][1]);
            atomicAdd(&g_num[(size_t)(R + 8) * OUT_FEAT + col],     acc[nt][2]);
            atomicAdd(&g_num[(size_t)(R + 8) * OUT_FEAT + col + 1], acc[nt][3]);
            acc[nt][0] = acc[nt][1] = acc[nt][2] = acc[nt][3] = 0.f;
        }
        ds0 = 0.f; ds1 = 0.f;
    };

    // divide + elu + store for row-block rb (run by the LAST finisher CTA)
    auto finalize_rb = [&](int rb) {
        const float4* num4 = (const float4*)g_num;
        float4* out4 = (float4*)out;
        int base = rb * 128 * (OUT_FEAT / 4);   // 2048 float4 per rb
#pragma unroll
        for (int k = 0; k < 8; k++) {
            int g = base + tid + k * 256;
            float4 n = num4[g];
            float inv = __fdividef(1.f, fmaxf(g_den[g >> 4], 1e-30f));
            float4 o; float v;
            v = n.x * inv; o.x = v > 0.f ? v : __expf(v) - 1.f;
            v = n.y * inv; o.y = v > 0.f ? v : __expf(v) - 1.f;
            v = n.z * inv; o.z = v > 0.f ? v : __expf(v) - 1.f;
            v = n.w * inv; o.w = v > 0.f ? v : __expf(v) - 1.f;
            out4[g] = o;
        }
    };

    // flush rb + completion handshake; last finisher finalizes the rb
    auto finish_rb = [&](int rb) {
        flush(rb);
        __threadfence();                        // make this CTA's atomics visible
        __syncthreads();
        if (tid == 0) {
            int contributors = c_of(rb * 256 + 255) - c_of(rb * 256) + 1;
            int old = atomicAdd(&g_cnt[rb], 1);
            s_last = (old == contributors - 1);
        }
        __syncthreads();
        if (s_last) {
            __threadfence();                    // acquire others' atomics
            finalize_rb(rb);
        }
    };

    // prologue: prefetch up to 2 tiles
    int nissue = t1 - t0 < 2 ? t1 - t0 : 2;
    for (int k = 0; k < nissue; k++) issue_tile((t0 + k) % 3, t0 + k);

    for (int t = t0; t < t1; t++) {
        if (t + 1 < t1) { CP_WAIT(1); }
        else            { CP_WAIT(0); }
        __syncthreads();                        // tile t visible; (t-1)%3 free
        if (t + 2 < t1) issue_tile((t + 2) % 3, t + 2);

        int rb = t >> 8;
        if (rb != cur_rb) {
            finish_rb(cur_rb);
            cur_rb = rb;
            egs0 = g_EGs[rb * 128 + w * 16 + r];
            egs1 = g_EGs[rb * 128 + w * 16 + r + 8];
        }

        int b = t % 3;
        const char* ab = sm + OFF_ADJ(b);
        const char* hb = sm + OFF_H(b);
        const float2* eb = (const float2*)(sm + OFF_EG(b));

#pragma unroll
        for (int kk = 0; kk < 2; kk++) {
            int c = kk * 4 + q;
            int cs = c ^ ((r & 1) << 2);        // rows r and r+8: same parity
            int colb = cs * 16;
            int4 avA = *(const int4*)(ab + (w * 16 + r) * ADJROW + colb);
            int4 avB = *(const int4*)(ab + (w * 16 + r + 8) * ADJROW + colb);
            int jloc = kk * 16 + 4 * q;
            float4 egA = *(const float4*)&eb[jloc];     // E,G: j, j+1
            float4 egB = *(const float4*)&eb[jloc + 2]; // E,G: j+2, j+3

            float p00 = avA.x ? fmaxf(egs0.x * egA.x, egs0.y * egA.y) : 0.f;
            float p01 = avA.y ? fmaxf(egs0.x * egA.z, egs0.y * egA.w) : 0.f;
            float p02 = avA.z ? fmaxf(egs0.x * egB.x, egs0.y * egB.y) : 0.f;
            float p03 = avA.w ? fmaxf(egs0.x * egB.z, egs0.y * egB.w) : 0.f;
            float p10 = avB.x ? fmaxf(egs1.x * egA.x, egs1.y * egA.y) : 0.f;
            float p11 = avB.y ? fmaxf(egs1.x * egA.z, egs1.y * egA.w) : 0.f;
            float p12 = avB.z ? fmaxf(egs1.x * egB.x, egs1.y * egB.y) : 0.f;
            float p13 = avB.w ? fmaxf(egs1.x * egB.z, egs1.y * egB.w) : 0.f;

            ds0 += (p00 + p01) + (p02 + p03);
            ds1 += (p10 + p11) + (p12 + p13);

            uint32_t A0 = packh2(p00, p01);
            uint32_t A1 = packh2(p10, p11);
            uint32_t A2 = packh2(p02, p03);
            uint32_t A3 = packh2(p12, p13);

            int ko = kk * 32 + q * 8;
#pragma unroll
            for (int nt = 0; nt < 8; nt++) {
                uint2 bb = *(const uint2*)(hb + (nt * 8 + r) * HROW + ko);
                mma16816(acc[nt], A0, A1, A2, A3, bb.x, bb.y);
            }
        }
    }

    finish_rb(cur_rb);
}

// =========================================================================
extern "C" void kernel_launch(void* const* d_in, const int* in_sizes, int n_in,
                              void* d_out, int out_size) {
    const float* x   = (const float*)d_in[0];
    const int*   adj = (const int*)d_in[1];
    const float* W   = (const float*)d_in[2];
    const float* a   = (const float*)d_in[3];
    float* out = (float*)d_out;

    cudaFuncSetAttribute(prep_kernel, cudaFuncAttributeMaxDynamicSharedMemorySize,
                         PREP_SMEM);
    cudaFuncSetAttribute(attn_kernel, cudaFuncAttributeMaxDynamicSharedMemorySize,
                         ATTN_SMEM);

    zero_kernel<<<(NT * OUT_FEAT) / 4 / 256, 256>>>();
    prep_kernel<<<NT / 32, 256, PREP_SMEM>>>(x, W, a);
    attn_kernel<<<WORKERS, 256, ATTN_SMEM>>>(adj, out);
}

// round 17
// speedup vs baseline: 1.3437x; 1.3437x over previous
#include <cuda_runtime.h>
#include <cuda_fp16.h>
#include <cstdint>
#include <cstddef>

// ============================================================
// GAT attention head, N=8192, IN_F=128, OUT_F=64
//  h = X@W ; e = LeakyReLU(fs_i + fd_j) masked by adj ; softmax ; P@h ; elu
//
// exp(LR(fs+fd)) = max(E_i*E_j, G_i*G_j) -> no exp in N^2 loop.
// Fixed-max softmax -> single pass; fp16 P/h via mma.sync.m16n8k16.
//
// PERSISTENT: 444 CTAs (3/SM) own static contiguous ranges of 16384 tiles
// (64 row-blocks x 256 j-tiles of 32) -> 99.7% utilization; flush by
// atomicAdd on row-block change. Warp = 16 rows x 64 feats (M=16, lean
// registers -> 3 CTAs/SM). 3-stage cp.async pipeline, distance 2:
//   wait_group(1) ; syncthreads ; issue(t+2) ; compute(t)
// adj XOR-4 chunk swizzle (odd rows swap 64B halves): zero padding,
// LDS.128 conflict-free. Finalize: separate kernel, fast-math divide+elu.
// ============================================================

#define NT 8192
#define IN_FEAT 128
#define OUT_FEAT 64
#define JTILE 32
#define TOTAL_TILES 16384            // 64 rb x 256 j-tiles
#define WORKERS 444                  // 3 per SM x 148
#define ADJROW 128                   // 32*4, no pad (swizzled)
#define HROW 96                      // 32*2 + 32 pad: LDS.64 conflict-free

#define ADJ_BYTES (128 * ADJROW)     // 16384
#define H_BYTES   (OUT_FEAT * HROW)  // 6144
#define EG_BYTES  (JTILE * 8)        // 256
#define NSTAGE 3
#define OFF_ADJ(i) ((i) * ADJ_BYTES)
#define OFF_H(i)   (NSTAGE * ADJ_BYTES + (i) * H_BYTES)
#define OFF_EG(i)  (NSTAGE * ADJ_BYTES + NSTAGE * H_BYTES + (i) * EG_BYTES)
#define ATTN_SMEM  (NSTAGE * (ADJ_BYTES + H_BYTES + EG_BYTES))   // 68352

#define PREP_WS   0
#define PREP_XS   (IN_FEAT * OUT_FEAT * 4)            // 32768
#define PREP_HS   (PREP_XS + 32 * IN_FEAT * 4)        // 49152
#define HS_STRIDE 34
#define PREP_SMEM (PREP_HS + OUT_FEAT * HS_STRIDE * 2) // 53504

// ---------------- scratch (static device arrays; no allocation) ----------
__device__ __half g_ht[OUT_FEAT * NT];
__device__ float2 g_EGs[NT];
__device__ float2 g_EGd[NT];
__device__ float  g_num[NT * OUT_FEAT];
__device__ float  g_den[NT];

// ---------------- helpers ------------------------------------------------
__device__ __forceinline__ uint32_t smem_u32(const void* p) {
    uint32_t a;
    asm("{ .reg .u64 t; cvta.to.shared.u64 t, %1; cvt.u32.u64 %0, t; }"
        : "=r"(a) : "l"(p));
    return a;
}
__device__ __forceinline__ void cp16(uint32_t dst, const void* src) {
    asm volatile("cp.async.cg.shared.global [%0], [%1], 16;" :: "r"(dst), "l"(src));
}
__device__ __forceinline__ void cp8(uint32_t dst, const void* src) {
    asm volatile("cp.async.ca.shared.global [%0], [%1], 8;" :: "r"(dst), "l"(src));
}
#define CP_COMMIT() asm volatile("cp.async.commit_group;" ::: "memory")
#define CP_WAIT(n)  asm volatile("cp.async.wait_group %0;" :: "n"(n) : "memory")

__device__ __forceinline__ void mma16816(float* d, uint32_t a0, uint32_t a1,
                                         uint32_t a2, uint32_t a3,
                                         uint32_t b0, uint32_t b1) {
    asm volatile(
        "mma.sync.aligned.m16n8k16.row.col.f32.f16.f16.f32 "
        "{%0,%1,%2,%3}, {%4,%5,%6,%7}, {%8,%9}, {%0,%1,%2,%3};"
        : "+f"(d[0]), "+f"(d[1]), "+f"(d[2]), "+f"(d[3])
        : "r"(a0), "r"(a1), "r"(a2), "r"(a3), "r"(b0), "r"(b1));
}
__device__ __forceinline__ uint32_t packh2(float x, float y) {
    __half2 h = __floats2half2_rn(x, y);
    return *reinterpret_cast<uint32_t*>(&h);
}

// =========================================================================
// Kernel 0: zero accumulators
// =========================================================================
__global__ void __launch_bounds__(256) zero_kernel() {
    int gid = blockIdx.x * 256 + threadIdx.x;
    ((float4*)g_num)[gid] = make_float4(0.f, 0.f, 0.f, 0.f);
    if (gid < NT / 4)
        ((float4*)g_den)[gid] = make_float4(0.f, 0.f, 0.f, 0.f);
}

// =========================================================================
// Kernel 1: h = X@W ; EG tables ; h^T fp16 (coalesced via smem transpose).
// R9 shape (measured 11.07us): 256 blocks x 256 threads, 4 rows/warp.
// =========================================================================
__global__ void __launch_bounds__(256) prep_kernel(const float* __restrict__ x,
                                                   const float* __restrict__ W,
                                                   const float* __restrict__ a) {
    extern __shared__ __align__(16) char sm[];
    float*  Ws = (float*)(sm + PREP_WS);
    float*  xs = (float*)(sm + PREP_XS);
    __half* hs = (__half*)(sm + PREP_HS);   // [64 f][34]

    int tid = threadIdx.x;
    int i0 = blockIdx.x * 32;

    {
        const float4* W4 = (const float4*)W;
        float4* Ws4 = (float4*)Ws;
#pragma unroll
        for (int u = 0; u < 8; u++) Ws4[tid + u * 256] = W4[tid + u * 256];
        const float4* x4 = (const float4*)(x + (size_t)i0 * IN_FEAT);
        float4* xs4 = (float4*)xs;
#pragma unroll
        for (int u = 0; u < 4; u++) xs4[tid + u * 256] = x4[tid + u * 256];
    }
    __syncthreads();

    int w = tid >> 5, l = tid & 31;
    float acc[4][2];
#pragma unroll
    for (int rr = 0; rr < 4; rr++) { acc[rr][0] = 0.f; acc[rr][1] = 0.f; }

#pragma unroll 4
    for (int k4 = 0; k4 < IN_FEAT; k4 += 4) {
        float2 wv[4];
#pragma unroll
        for (int kk = 0; kk < 4; kk++)
            wv[kk] = *(const float2*)&Ws[(k4 + kk) * OUT_FEAT + 2 * l];
#pragma unroll
        for (int rr = 0; rr < 4; rr++) {
            float4 xv = *(const float4*)&xs[(w * 4 + rr) * IN_FEAT + k4];
            acc[rr][0] = fmaf(xv.x, wv[0].x, acc[rr][0]);
            acc[rr][1] = fmaf(xv.x, wv[0].y, acc[rr][1]);
            acc[rr][0] = fmaf(xv.y, wv[1].x, acc[rr][0]);
            acc[rr][1] = fmaf(xv.y, wv[1].y, acc[rr][1]);
            acc[rr][0] = fmaf(xv.z, wv[2].x, acc[rr][0]);
            acc[rr][1] = fmaf(xv.z, wv[2].y, acc[rr][1]);
            acc[rr][0] = fmaf(xv.w, wv[3].x, acc[rr][0]);
            acc[rr][1] = fmaf(xv.w, wv[3].y, acc[rr][1]);
        }
    }

#pragma unroll
    for (int rr = 0; rr < 4; rr++) {
        int il = w * 4 + rr;
        hs[(2 * l) * HS_STRIDE + il]     = __float2half(acc[rr][0]);
        hs[(2 * l + 1) * HS_STRIDE + il] = __float2half(acc[rr][1]);
    }

    float a0 = a[2 * l], a1 = a[2 * l + 1];
    float a2 = a[OUT_FEAT + 2 * l], a3 = a[OUT_FEAT + 2 * l + 1];
#pragma unroll
    for (int rr = 0; rr < 4; rr++) {
        float s = acc[rr][0] * a0 + acc[rr][1] * a1;
        float d = acc[rr][0] * a2 + acc[rr][1] * a3;
#pragma unroll
        for (int off = 16; off; off >>= 1) {
            s += __shfl_xor_sync(0xFFFFFFFFu, s, off);
            d += __shfl_xor_sync(0xFFFFFFFFu, d, off);
        }
        if (l == 0) {
            int i = i0 + w * 4 + rr;
            g_EGs[i] = make_float2(expf(s), expf(0.2f * s));
            g_EGd[i] = make_float2(expf(d), expf(0.2f * d));
        }
    }
    __syncthreads();

#pragma unroll
    for (int u = 0; u < 4; u++) {
        int id = tid + u * 256;
        int f = id >> 4, c = id & 15;
        uint32_t v = *(const uint32_t*)&hs[f * HS_STRIDE + 2 * c];
        *(uint32_t*)&g_ht[(size_t)f * NT + i0 + 2 * c] = v;
    }
}

// =========================================================================
// Kernel 2: persistent fused attention, 3-stage pipeline, 3 CTAs/SM.
// 444 CTAs x 256 thr. Warp w: rows w*16..w*16+15, all 32 j (2 kk steps).
// (byte-identical to R15's attn — measured best)
// =========================================================================
__global__ void __launch_bounds__(256, 3) attn_kernel(const int* __restrict__ adj) {
    extern __shared__ __align__(16) char sm[];
    uint32_t sb = smem_u32(sm);

    int tid = threadIdx.x, w = tid >> 5, lane = tid & 31;
    int r = lane >> 2, q = lane & 3;
    int cta = blockIdx.x;

    int t0 = (int)(((long long)cta * TOTAL_TILES) / WORKERS);
    int t1 = (int)(((long long)(cta + 1) * TOTAL_TILES) / WORKERS);

    float acc[8][4];
#pragma unroll
    for (int nt = 0; nt < 8; nt++)
#pragma unroll
        for (int v = 0; v < 4; v++) acc[nt][v] = 0.f;
    float ds0 = 0.f, ds1 = 0.f;

    auto issue_tile = [&](int buf, int t) {
        int i0t = (t >> 8) * 128;
        int j0t = (t & 255) * JTILE;
        uint32_t ab = sb + OFF_ADJ(buf);
        uint32_t hb = sb + OFF_H(buf);
        uint32_t eb = sb + OFF_EG(buf);
#pragma unroll
        for (int u = 0; u < 4; u++) {
            int id = tid + u * 256;
            int row = id >> 3, c = id & 7;
            int cs = c ^ ((row & 1) << 2);      // odd rows swap 64B halves
            cp16(ab + row * ADJROW + cs * 16,
                 &adj[(size_t)(i0t + row) * NT + j0t + c * 4]);
        }
        {
            int f = tid >> 2, c = tid & 3;
            cp16(hb + f * HROW + c * 16,
                 &g_ht[(size_t)f * NT + j0t + c * 8]);
        }
        if (tid < JTILE) cp8(eb + tid * 8, &g_EGd[j0t + tid]);
        CP_COMMIT();
    };

    int cur_rb = t0 >> 8;
    float2 egs0 = g_EGs[cur_rb * 128 + w * 16 + r];
    float2 egs1 = g_EGs[cur_rb * 128 + w * 16 + r + 8];

    auto flush = [&](int rb) {
        float d0 = ds0, d1 = ds1;
        d0 += __shfl_xor_sync(0xFFFFFFFFu, d0, 1);
        d0 += __shfl_xor_sync(0xFFFFFFFFu, d0, 2);
        d1 += __shfl_xor_sync(0xFFFFFFFFu, d1, 1);
        d1 += __shfl_xor_sync(0xFFFFFFFFu, d1, 2);
        int R = rb * 128 + w * 16 + r;
        if (q == 0) {
            atomicAdd(&g_den[R], d0);
            atomicAdd(&g_den[R + 8], d1);
        }
#pragma unroll
        for (int nt = 0; nt < 8; nt++) {
            int col = nt * 8 + q * 2;
            atomicAdd(&g_num[(size_t)R * OUT_FEAT + col],           acc[nt][0]);
            atomicAdd(&g_num[(size_t)R * OUT_FEAT + col + 1],       acc[nt][1]);
            atomicAdd(&g_num[(size_t)(R + 8) * OUT_FEAT + col],     acc[nt][2]);
            atomicAdd(&g_num[(size_t)(R + 8) * OUT_FEAT + col + 1], acc[nt][3]);
            acc[nt][0] = acc[nt][1] = acc[nt][2] = acc[nt][3] = 0.f;
        }
        ds0 = 0.f; ds1 = 0.f;
    };

    int nissue = t1 - t0 < 2 ? t1 - t0 : 2;
    for (int k = 0; k < nissue; k++) issue_tile((t0 + k) % 3, t0 + k);

    for (int t = t0; t < t1; t++) {
        if (t + 1 < t1) { CP_WAIT(1); }
        else            { CP_WAIT(0); }
        __syncthreads();
        if (t + 2 < t1) issue_tile((t + 2) % 3, t + 2);

        int rb = t >> 8;
        if (rb != cur_rb) {
            flush(cur_rb);
            cur_rb = rb;
            egs0 = g_EGs[rb * 128 + w * 16 + r];
            egs1 = g_EGs[rb * 128 + w * 16 + r + 8];
        }

        int b = t % 3;
        const char* ab = sm + OFF_ADJ(b);
        const char* hb = sm + OFF_H(b);
        const float2* eb = (const float2*)(sm + OFF_EG(b));

#pragma unroll
        for (int kk = 0; kk < 2; kk++) {
            int c = kk * 4 + q;
            int cs = c ^ ((r & 1) << 2);
            int colb = cs * 16;
            int4 avA = *(const int4*)(ab + (w * 16 + r) * ADJROW + colb);
            int4 avB = *(const int4*)(ab + (w * 16 + r + 8) * ADJROW + colb);
            int jloc = kk * 16 + 4 * q;
            float4 egA = *(const float4*)&eb[jloc];
            float4 egB = *(const float4*)&eb[jloc + 2];

            float p00 = avA.x ? fmaxf(egs0.x * egA.x, egs0.y * egA.y) : 0.f;
            float p01 = avA.y ? fmaxf(egs0.x * egA.z, egs0.y * egA.w) : 0.f;
            float p02 = avA.z ? fmaxf(egs0.x * egB.x, egs0.y * egB.y) : 0.f;
            float p03 = avA.w ? fmaxf(egs0.x * egB.z, egs0.y * egB.w) : 0.f;
            float p10 = avB.x ? fmaxf(egs1.x * egA.x, egs1.y * egA.y) : 0.f;
            float p11 = avB.y ? fmaxf(egs1.x * egA.z, egs1.y * egA.w) : 0.f;
            float p12 = avB.z ? fmaxf(egs1.x * egB.x, egs1.y * egB.y) : 0.f;
            float p13 = avB.w ? fmaxf(egs1.x * egB.z, egs1.y * egB.w) : 0.f;

            ds0 += (p00 + p01) + (p02 + p03);
            ds1 += (p10 + p11) + (p12 + p13);

            uint32_t A0 = packh2(p00, p01);
            uint32_t A1 = packh2(p10, p11);
            uint32_t A2 = packh2(p02, p03);
            uint32_t A3 = packh2(p12, p13);

            int ko = kk * 32 + q * 8;
#pragma unroll
            for (int nt = 0; nt < 8; nt++) {
                uint2 bb = *(const uint2*)(hb + (nt * 8 + r) * HROW + ko);
                mma16816(acc[nt], A0, A1, A2, A3, bb.x, bb.y);
            }
        }
    }

    flush(cur_rb);
}

// =========================================================================
// Kernel 3: divide + elu — fast math (__fdividef, __expf), 512 blocks
// =========================================================================
__global__ void __launch_bounds__(256) finalize_kernel(float* __restrict__ out) {
    int gid = blockIdx.x * 256 + threadIdx.x;        // 131072 threads, 1 float4 each
    float4 n = ((const float4*)g_num)[gid];
    float inv = __fdividef(1.f, fmaxf(g_den[gid >> 4], 1e-30f));
    float4 o; float v;
    v = n.x * inv; o.x = v > 0.f ? v : __expf(v) - 1.f;
    v = n.y * inv; o.y = v > 0.f ? v : __expf(v) - 1.f;
    v = n.z * inv; o.z = v > 0.f ? v : __expf(v) - 1.f;
    v = n.w * inv; o.w = v > 0.f ? v : __expf(v) - 1.f;
    ((float4*)out)[gid] = o;
}

// =========================================================================
extern "C" void kernel_launch(void* const* d_in, const int* in_sizes, int n_in,
                              void* d_out, int out_size) {
    const float* x   = (const float*)d_in[0];
    const int*   adj = (const int*)d_in[1];
    const float* W   = (const float*)d_in[2];
    const float* a   = (const float*)d_in[3];
    float* out = (float*)d_out;

    cudaFuncSetAttribute(prep_kernel, cudaFuncAttributeMaxDynamicSharedMemorySize,
                         PREP_SMEM);
    cudaFuncSetAttribute(attn_kernel, cudaFuncAttributeMaxDynamicSharedMemorySize,
                         ATTN_SMEM);

    zero_kernel<<<(NT * OUT_FEAT) / 4 / 256, 256>>>();
    prep_kernel<<<NT / 32, 256, PREP_SMEM>>>(x, W, a);
    attn_kernel<<<WORKERS, 256, ATTN_SMEM>>>(adj);
    finalize_kernel<<<(NT * OUT_FEAT) / 4 / 256, 256>>>(out);
}